// round 3
// baseline (speedup 1.0000x reference)
#include <cuda_runtime.h>
#include <cstdint>

#define DD 128
#define N_MAX 50000

// scratch for aggregated features h = segment_sum(feature[src], dst)
// float4-typed => guaranteed 16B alignment for vector loads/reduction atomics
static __device__ float4 g_h4[(size_t)N_MAX * (DD / 4)];

// ---------------------------------------------------------------------------
// Kernel 1: zero the scratch accumulator
// ---------------------------------------------------------------------------
__global__ void k_zero(int n4) {
    int i = blockIdx.x * blockDim.x + threadIdx.x;
    if (i < n4) g_h4[i] = make_float4(0.f, 0.f, 0.f, 0.f);
}

// ---------------------------------------------------------------------------
// Index dtype detection: the reference declares int64 indices, but JAX with
// x64 disabled silently emits int32. Inspect the first 4 elements as int64;
// if any falls outside [0, N) the buffer is int32. (int32 data viewed as
// int64 packs two indices -> >= 2^32 unless the odd index is exactly 0.)
// ---------------------------------------------------------------------------
__device__ __forceinline__ bool detect_i64(const void* p, int N) {
    const long long* q = (const long long*)p;
    bool ok = true;
    #pragma unroll
    for (int i = 0; i < 4; i++) {
        long long v = __ldg(&q[i]);
        if (v < 0 || v >= N) ok = false;
    }
    return ok;
}

__device__ __forceinline__ int load_idx(const void* p, int i, bool e64, int N) {
    long long v = e64 ? ((const long long*)p)[i] : (long long)((const int*)p)[i];
    // clamp: never crash on unexpected data; rel_err will expose mismatch
    if (v < 0) v = 0;
    if (v >= N) v = N - 1;
    return (int)v;
}

// ---------------------------------------------------------------------------
// Kernel 2: gather + scatter-add. One warp per edge; each lane moves one
// float4 (16B). Vectorized reduction atomics (sm_90+) quarter the atomic
// op count vs scalar atomicAdd.
// ---------------------------------------------------------------------------
__global__ void k_scatter(const float* __restrict__ feat,
                          const void* __restrict__ src,
                          const void* __restrict__ dst,
                          int E, int N) {
    int gid = blockIdx.x * blockDim.x + threadIdx.x;
    int e = gid >> 5;
    int c = gid & 31;
    if (e >= E) return;
    bool e64 = detect_i64(src, N);     // warp-uniform, L1-hit loads
    int s = load_idx(src, e, e64, N);  // all 32 lanes same addr -> broadcast
    int d = load_idx(dst, e, e64, N);
    float4 v = reinterpret_cast<const float4*>(feat)[(size_t)s * 32 + c];
    float4* p = g_h4 + (size_t)d * 32 + c;
    asm volatile("red.global.add.v4.f32 [%0], {%1,%2,%3,%4};"
                 :: "l"(p), "f"(v.x), "f"(v.y), "f"(v.z), "f"(v.w)
                 : "memory");
}

// ---------------------------------------------------------------------------
// Kernel 3: fused  out = relu(layernorm((h @ W^T) * snorm) * gamma + beta)
//
// W^T staged in smem as Wt[k][j] (conflict-free float4 reads, lane -> 4 cols).
// Each warp processes 4 rows at a time (register blocking 4 rows x 4 cols),
// row data staged in smem and read via broadcast LDS. Epilogue layernorm via
// warp shuffles (row fully owned by one warp).
// ---------------------------------------------------------------------------
__global__ __launch_bounds__(256, 2) void k_gemm_norm(
    const float* __restrict__ Wg,     // [D,D] row-major: W[j*D+k]
    const float* __restrict__ snorm,  // [N]
    const float* __restrict__ gamma,  // [D]
    const float* __restrict__ beta,   // [D]
    float* __restrict__ out,          // [N,D]
    int N)
{
    extern __shared__ float sm[];
    float* Wt = sm;                   // 16384 floats: Wt[k*128 + j] = W[j][k]
    float* rowbuf = sm + DD * DD;     // 8 warps * 4 rows * 128 floats

    // load + transpose W into smem (coalesced global reads)
    for (int idx = threadIdx.x; idx < DD * DD; idx += blockDim.x) {
        int j = idx >> 7;
        int k = idx & 127;
        Wt[k * DD + j] = Wg[idx];
    }
    __syncthreads();

    const int warp = threadIdx.x >> 5;
    const int lane = threadIdx.x & 31;
    const float4 gm = reinterpret_cast<const float4*>(gamma)[lane];
    const float4 bt = reinterpret_cast<const float4*>(beta)[lane];
    float* rb = rowbuf + warp * (4 * DD);
    const float4* Wt4 = reinterpret_cast<const float4*>(Wt);

    for (int row0 = blockIdx.x * 32 + warp * 4; row0 < N;
         row0 += gridDim.x * 32) {

        // stage this warp's 4 rows of h into smem
        #pragma unroll
        for (int r = 0; r < 4; r++) {
            int row = row0 + r;
            if (row >= N) row = N - 1;  // clamp (results discarded)
            reinterpret_cast<float4*>(rb)[r * 32 + lane] =
                g_h4[(size_t)row * 32 + lane];
        }
        __syncwarp();

        float acc[4][4];
        #pragma unroll
        for (int r = 0; r < 4; r++)
            #pragma unroll
            for (int u = 0; u < 4; u++) acc[r][u] = 0.f;

        #pragma unroll 4
        for (int k = 0; k < DD; k += 4) {
            // broadcast loads of the 4 rows' a-values (same addr all lanes)
            float4 a0 = *reinterpret_cast<const float4*>(rb + 0 * DD + k);
            float4 a1 = *reinterpret_cast<const float4*>(rb + 1 * DD + k);
            float4 a2 = *reinterpret_cast<const float4*>(rb + 2 * DD + k);
            float4 a3 = *reinterpret_cast<const float4*>(rb + 3 * DD + k);
            #pragma unroll
            for (int kk = 0; kk < 4; kk++) {
                float4 w = Wt4[(k + kk) * 32 + lane];
                float av0 = (&a0.x)[kk];
                float av1 = (&a1.x)[kk];
                float av2 = (&a2.x)[kk];
                float av3 = (&a3.x)[kk];
                acc[0][0] += av0 * w.x; acc[0][1] += av0 * w.y;
                acc[0][2] += av0 * w.z; acc[0][3] += av0 * w.w;
                acc[1][0] += av1 * w.x; acc[1][1] += av1 * w.y;
                acc[1][2] += av1 * w.z; acc[1][3] += av1 * w.w;
                acc[2][0] += av2 * w.x; acc[2][1] += av2 * w.y;
                acc[2][2] += av2 * w.z; acc[2][3] += av2 * w.w;
                acc[3][0] += av3 * w.x; acc[3][1] += av3 * w.y;
                acc[3][2] += av3 * w.z; acc[3][3] += av3 * w.w;
            }
        }

        // fused epilogue: snorm scale -> layernorm -> affine -> relu
        #pragma unroll
        for (int r = 0; r < 4; r++) {
            int row = row0 + r;
            if (row >= N) break;
            float s = __ldg(snorm + row);
            float x0 = acc[r][0] * s, x1 = acc[r][1] * s;
            float x2 = acc[r][2] * s, x3 = acc[r][3] * s;
            float sum = x0 + x1 + x2 + x3;
            float sq  = x0 * x0 + x1 * x1 + x2 * x2 + x3 * x3;
            #pragma unroll
            for (int o = 16; o > 0; o >>= 1) {
                sum += __shfl_xor_sync(0xffffffffu, sum, o);
                sq  += __shfl_xor_sync(0xffffffffu, sq,  o);
            }
            float mean = sum * (1.0f / 128.0f);
            float var  = sq  * (1.0f / 128.0f) - mean * mean;
            float rstd = rsqrtf(var + 1e-5f);
            float4 o4;
            o4.x = fmaxf((x0 - mean) * rstd * gm.x + bt.x, 0.f);
            o4.y = fmaxf((x1 - mean) * rstd * gm.y + bt.y, 0.f);
            o4.z = fmaxf((x2 - mean) * rstd * gm.z + bt.z, 0.f);
            o4.w = fmaxf((x3 - mean) * rstd * gm.w + bt.w, 0.f);
            reinterpret_cast<float4*>(out)[(size_t)row * 32 + lane] = o4;
        }
        __syncwarp();
    }
}

// ---------------------------------------------------------------------------
extern "C" void kernel_launch(void* const* d_in, const int* in_sizes, int n_in,
                              void* d_out, int out_size) {
    const float* feature = (const float*)d_in[0];
    const float* snorm   = (const float*)d_in[1];
    const float* Wg      = (const float*)d_in[2];
    const float* gamma   = (const float*)d_in[3];
    const float* beta    = (const float*)d_in[4];
    const void*  src     = d_in[5];
    const void*  dst     = d_in[6];
    int N = in_sizes[1];            // snorm_n has N elements
    int E = in_sizes[5];
    float* out = (float*)d_out;

    // 1) zero accumulator
    int n4 = N * (DD / 4);
    k_zero<<<(n4 + 255) / 256, 256>>>(n4);

    // 2) gather + vector-atomic scatter: one warp per edge
    long long tot_threads = (long long)E * 32;
    int sblocks = (int)((tot_threads + 255) / 256);
    k_scatter<<<sblocks, 256>>>(feature, src, dst, E, N);

    // 3) fused GEMM + graphnorm + layernorm + relu (persistent grid)
    const int SMEM = (DD * DD + 8 * 4 * DD) * (int)sizeof(float);  // 80 KB
    cudaFuncSetAttribute(k_gemm_norm,
                         cudaFuncAttributeMaxDynamicSharedMemorySize, SMEM);
    k_gemm_norm<<<304, 256, SMEM>>>(Wg, snorm, gamma, beta, out, N);
}